// round 1
// baseline (speedup 1.0000x reference)
#include <cuda_runtime.h>
#include <math.h>

// Problem constants (fixed by the reference)
#define B_SIZE   2
#define S_LEN    2048
#define D_MODEL  2048
#define NHEAD    16
#define HD       128
#define ROWS     (B_SIZE * S_LEN)      // 4096
#define QKV_COLS (3 * D_MODEL)         // 6144

// Scratch (allocation-free rule: __device__ globals)
__device__ float g_qkv[(size_t)ROWS * QKV_COLS];   // ~100.7 MB
__device__ float g_ctx[(size_t)ROWS * D_MODEL];    // ~33.5 MB

// ============================================================================
// SGEMM (NT): C[m,n] = sum_k A[m,k] * B[n,k] + bias[n]
// A: [M,K] row-major, B: [N,K] row-major (i.e., C = A @ B^T + bias)
// 128x128 tile, BK=8, 256 threads, 8x8 micro-tile, float4 loads,
// register prefetch of next K-slab.
// ============================================================================
#define GBM 128
#define GBN 128
#define GBK 8
#define GTM 8
#define GTN 8

__global__ __launch_bounds__(256) void sgemm_nt_bias(
    const float* __restrict__ A, const float* __restrict__ B,
    const float* __restrict__ bias, float* __restrict__ C,
    int M, int N, int K)
{
    __shared__ float As[GBK][GBM];
    __shared__ float Bs[GBK][GBN];

    const int tid = threadIdx.x;
    const int m0 = blockIdx.y * GBM;
    const int n0 = blockIdx.x * GBN;

    const int lrow = tid >> 1;          // 0..127
    const int lk   = (tid & 1) * 4;     // 0 or 4

    const float* Aptr = A + (size_t)(m0 + lrow) * K + lk;
    const float* Bptr = B + (size_t)(n0 + lrow) * K + lk;

    const int trow = (tid >> 4) * GTM;  // 0..120
    const int tcol = (tid & 15) * GTN;  // 0..120

    float acc[GTM][GTN];
    #pragma unroll
    for (int i = 0; i < GTM; i++)
        #pragma unroll
        for (int j = 0; j < GTN; j++)
            acc[i][j] = 0.0f;

    const int nTiles = K / GBK;
    float4 a_next = *(const float4*)Aptr;
    float4 b_next = *(const float4*)Bptr;

    for (int t = 0; t < nTiles; ++t) {
        // Stage current slab into shared (transposed: [k][m])
        As[lk + 0][lrow] = a_next.x;
        As[lk + 1][lrow] = a_next.y;
        As[lk + 2][lrow] = a_next.z;
        As[lk + 3][lrow] = a_next.w;
        Bs[lk + 0][lrow] = b_next.x;
        Bs[lk + 1][lrow] = b_next.y;
        Bs[lk + 2][lrow] = b_next.z;
        Bs[lk + 3][lrow] = b_next.w;
        __syncthreads();

        // Prefetch next slab into registers (overlaps with compute)
        if (t + 1 < nTiles) {
            a_next = *(const float4*)(Aptr + (size_t)(t + 1) * GBK);
            b_next = *(const float4*)(Bptr + (size_t)(t + 1) * GBK);
        }

        #pragma unroll
        for (int k = 0; k < GBK; k++) {
            float ra[GTM], rb[GTN];
            float4 ra0 = *(const float4*)&As[k][trow];
            float4 ra1 = *(const float4*)&As[k][trow + 4];
            ra[0] = ra0.x; ra[1] = ra0.y; ra[2] = ra0.z; ra[3] = ra0.w;
            ra[4] = ra1.x; ra[5] = ra1.y; ra[6] = ra1.z; ra[7] = ra1.w;
            float4 rb0 = *(const float4*)&Bs[k][tcol];
            float4 rb1 = *(const float4*)&Bs[k][tcol + 4];
            rb[0] = rb0.x; rb[1] = rb0.y; rb[2] = rb0.z; rb[3] = rb0.w;
            rb[4] = rb1.x; rb[5] = rb1.y; rb[6] = rb1.z; rb[7] = rb1.w;
            #pragma unroll
            for (int i = 0; i < GTM; i++)
                #pragma unroll
                for (int j = 0; j < GTN; j++)
                    acc[i][j] = fmaf(ra[i], rb[j], acc[i][j]);
        }
        __syncthreads();
    }

    // Epilogue: add bias, write with float4
    #pragma unroll
    for (int i = 0; i < GTM; i++) {
        float* crow = C + (size_t)(m0 + trow + i) * N + n0 + tcol;
        const float* brow = bias + n0 + tcol;
        float4 o0, o1;
        o0.x = acc[i][0] + brow[0];
        o0.y = acc[i][1] + brow[1];
        o0.z = acc[i][2] + brow[2];
        o0.w = acc[i][3] + brow[3];
        o1.x = acc[i][4] + brow[4];
        o1.y = acc[i][5] + brow[5];
        o1.z = acc[i][6] + brow[6];
        o1.w = acc[i][7] + brow[7];
        *(float4*)(crow)     = o0;
        *(float4*)(crow + 4) = o1;
    }
}

// ============================================================================
// Causal flash attention over the qkv buffer.
// qkv layout: [ROWS, 6144] where row = b*S + s, cols [0,2048)=Q, [2048,4096)=K,
// [4096,6144)=V; head h occupies a 128-wide column slice.
// Block: 128 threads, 1 thread per query row. BN=32 keys per tile.
// Q tile in padded shared; acc[128] in registers; online softmax.
// Output: ctx[b*S+s, h*128+d]  ([B,S,D] with head-major columns).
// ============================================================================
#define AT_BM 128
#define AT_BN 32
#define QS_STRIDE 132   // 128 + 4 pad (float4-aligned, conflict-light)
#define SMEM_AT ((AT_BM * QS_STRIDE + 2 * AT_BN * HD) * 4)  // 100352 bytes

__global__ __launch_bounds__(128, 2) void flash_attn(
    const float* __restrict__ qkv, float* __restrict__ ctx)
{
    extern __shared__ float sm[];
    float* Qs = sm;                               // [128][132]
    float* Ks = Qs + AT_BM * QS_STRIDE;           // [32][128]
    float* Vs = Ks + AT_BN * HD;                  // [32][128]

    const int tid = threadIdx.x;
    const int q0  = blockIdx.x * AT_BM;
    const int bh  = blockIdx.y;
    const int b   = bh >> 4;
    const int h   = bh & 15;

    const size_t ROWSTRIDE = QKV_COLS;  // 6144
    const float* base = qkv + (size_t)b * S_LEN * ROWSTRIDE + (size_t)h * HD;

    // Load Q tile [128, 128] -> shared (padded rows)
    #pragma unroll
    for (int i = 0; i < 32; i++) {
        int idx = tid + 128 * i;        // 0..4095
        int row = idx >> 5;
        int c4  = idx & 31;
        float4 v = *(const float4*)(base + (size_t)(q0 + row) * ROWSTRIDE + c4 * 4);
        *(float4*)(Qs + row * QS_STRIDE + c4 * 4) = v;
    }
    __syncthreads();

    const int r = q0 + tid;             // this thread's query row
    float m = -INFINITY;
    float l = 0.0f;
    float acc[HD];
    #pragma unroll
    for (int d = 0; d < HD; d++) acc[d] = 0.0f;

    const float scale = 0.08838834764831845f;  // 128^-0.5

    const int nTiles = q0 / AT_BN + (AT_BM / AT_BN);  // keys up to q0+127
    for (int t = 0; t < nTiles; t++) {
        const int k0 = t * AT_BN;

        // Cooperative K/V tile load [32,128] each
        #pragma unroll
        for (int i = 0; i < 8; i++) {
            int idx = tid + 128 * i;    // 0..1023
            int row = idx >> 5;
            int c4  = idx & 31;
            const float* gk = base + (size_t)(k0 + row) * ROWSTRIDE + D_MODEL + c4 * 4;
            *(float4*)(Ks + row * HD + c4 * 4) = *(const float4*)gk;
            *(float4*)(Vs + row * HD + c4 * 4) = *(const float4*)(gk + D_MODEL);
        }
        __syncthreads();

        // Scores: s[j] = Q_row . K_j
        float s[AT_BN];
        #pragma unroll
        for (int j = 0; j < AT_BN; j++) s[j] = 0.0f;

        const float4* qrow = (const float4*)(Qs + tid * QS_STRIDE);
        #pragma unroll 4
        for (int d4 = 0; d4 < HD / 4; d4++) {
            float4 q4 = qrow[d4];
            #pragma unroll
            for (int j = 0; j < AT_BN; j++) {
                float4 k4 = *(const float4*)(Ks + j * HD + d4 * 4);
                s[j] = fmaf(q4.x, k4.x,
                        fmaf(q4.y, k4.y,
                         fmaf(q4.z, k4.z,
                          fmaf(q4.w, k4.w, s[j]))));
            }
        }

        // Scale + causal mask + tile max
        float tmax = -INFINITY;
        #pragma unroll
        for (int j = 0; j < AT_BN; j++) {
            float sv = s[j] * scale;
            if (k0 + j > r) sv = -INFINITY;
            s[j] = sv;
            tmax = fmaxf(tmax, sv);
        }

        const float newm = fmaxf(m, tmax);  // finite after tile 0 (k=0 <= r always)
        const float corr = expf(m - newm);

        float p[AT_BN];
        float psum = 0.0f;
        #pragma unroll
        for (int j = 0; j < AT_BN; j++) {
            p[j] = expf(s[j] - newm);       // masked -> exp(-inf) = 0
            psum += p[j];
        }
        l = l * corr + psum;
        m = newm;

        #pragma unroll
        for (int d = 0; d < HD; d++) acc[d] *= corr;

        // acc += P @ V_tile
        #pragma unroll
        for (int j = 0; j < AT_BN; j++) {
            const float pj = p[j];
            const float4* vrow = (const float4*)(Vs + j * HD);
            #pragma unroll
            for (int d4 = 0; d4 < HD / 4; d4++) {
                float4 v4 = vrow[d4];
                acc[4 * d4 + 0] = fmaf(pj, v4.x, acc[4 * d4 + 0]);
                acc[4 * d4 + 1] = fmaf(pj, v4.y, acc[4 * d4 + 1]);
                acc[4 * d4 + 2] = fmaf(pj, v4.z, acc[4 * d4 + 2]);
                acc[4 * d4 + 3] = fmaf(pj, v4.w, acc[4 * d4 + 3]);
            }
        }
        __syncthreads();   // protect Ks/Vs before next tile's load
    }

    // Normalize and write ctx[b*S+r, h*128 + d]
    const float inv = 1.0f / l;
    float* outp = ctx + (size_t)(b * S_LEN + r) * D_MODEL + (size_t)h * HD;
    #pragma unroll
    for (int d4 = 0; d4 < HD / 4; d4++) {
        float4 o;
        o.x = acc[4 * d4 + 0] * inv;
        o.y = acc[4 * d4 + 1] * inv;
        o.z = acc[4 * d4 + 2] * inv;
        o.w = acc[4 * d4 + 3] * inv;
        *(float4*)(outp + d4 * 4) = o;
    }
}

// ============================================================================
// kernel_launch
// Inputs (metadata order): 0=x [B,S,D] f32, 1=mask (ignored; causal is known),
// 2=wqkv_w [6144,2048], 3=wqkv_b [6144], 4=out_w [2048,2048], 5=out_b [2048]
// Output: [B,S,D] f32
// ============================================================================
extern "C" void kernel_launch(void* const* d_in, const int* in_sizes, int n_in,
                              void* d_out, int out_size)
{
    (void)in_sizes; (void)n_in; (void)out_size;
    const float* x      = (const float*)d_in[0];
    const float* wqkv_w = (const float*)d_in[2];
    const float* wqkv_b = (const float*)d_in[3];
    const float* out_w  = (const float*)d_in[4];
    const float* out_b  = (const float*)d_in[5];
    float* out = (float*)d_out;

    float* qkv = nullptr;
    float* ctx = nullptr;
    cudaGetSymbolAddress((void**)&qkv, g_qkv);
    cudaGetSymbolAddress((void**)&ctx, g_ctx);

    // 1) QKV projection: [4096,2048] @ [6144,2048]^T + b -> [4096,6144]
    {
        dim3 grid(QKV_COLS / GBN, ROWS / GBM);   // (48, 32)
        sgemm_nt_bias<<<grid, 256>>>(x, wqkv_w, wqkv_b, qkv,
                                     ROWS, QKV_COLS, D_MODEL);
    }

    // 2) Causal attention per (qblock, b*h)
    {
        cudaFuncSetAttribute(flash_attn,
                             cudaFuncAttributeMaxDynamicSharedMemorySize,
                             SMEM_AT);
        dim3 grid(S_LEN / AT_BM, B_SIZE * NHEAD);  // (16, 32)
        flash_attn<<<grid, 128, SMEM_AT>>>(qkv, ctx);
    }

    // 3) Output projection: [4096,2048] @ [2048,2048]^T + b -> d_out
    {
        dim3 grid(D_MODEL / GBN, ROWS / GBM);    // (16, 32)
        sgemm_nt_bias<<<grid, 256>>>(ctx, out_w, out_b, out,
                                     ROWS, D_MODEL, D_MODEL);
    }
}

// round 6
// speedup vs baseline: 1.4549x; 1.4549x over previous
#include <cuda_runtime.h>
#include <cuda_bf16.h>
#include <math.h>
#include <stdint.h>

// Problem constants
#define B_SIZE   2
#define S_LEN    2048
#define D_MODEL  2048
#define NHEAD    16
#define HD       128
#define ROWS     (B_SIZE * S_LEN)      // 4096
#define QKV_COLS (3 * D_MODEL)         // 6144
#define KDIM     2048
#define CATSTRIDE (2 * KDIM)           // 4096 (hi block | lo block)

// ---------------------------------------------------------------------------
// Scratch (__device__ globals; no allocation allowed)
// ---------------------------------------------------------------------------
__device__ float         g_qkv[(size_t)ROWS * QKV_COLS];
__device__ float         g_ctx[(size_t)ROWS * D_MODEL];
__device__ __nv_bfloat16 g_x_cat[(size_t)ROWS * CATSTRIDE];
__device__ __nv_bfloat16 g_wqkv_cat[(size_t)QKV_COLS * CATSTRIDE];
__device__ __nv_bfloat16 g_wo_cat[(size_t)D_MODEL * CATSTRIDE];
__device__ __nv_bfloat16 g_ctx_cat[(size_t)ROWS * CATSTRIDE];

#define SMEM_SWIZZLE_128B(off) ((off) ^ (((off) >> 3) & 0x70))

__device__ __forceinline__ uint32_t smem_to_u32(const void* p) {
    uint32_t a;
    asm("{ .reg .u64 t; cvta.to.shared.u64 t, %1; cvt.u32.u64 %0, t; }"
        : "=r"(a) : "l"(p));
    return a;
}

__device__ __forceinline__ void ldsm_x4(uint32_t& r0, uint32_t& r1,
                                        uint32_t& r2, uint32_t& r3,
                                        uint32_t addr) {
    asm volatile("ldmatrix.sync.aligned.m8n8.x4.shared.b16 {%0,%1,%2,%3}, [%4];"
                 : "=r"(r0), "=r"(r1), "=r"(r2), "=r"(r3) : "r"(addr));
}

__device__ __forceinline__ void mma_bf16_16816(float* c, const uint32_t* a,
                                               uint32_t b0, uint32_t b1) {
    asm volatile(
        "mma.sync.aligned.m16n8k16.row.col.f32.bf16.bf16.f32 "
        "{%0,%1,%2,%3}, {%4,%5,%6,%7}, {%8,%9}, {%0,%1,%2,%3};"
        : "+f"(c[0]), "+f"(c[1]), "+f"(c[2]), "+f"(c[3])
        : "r"(a[0]), "r"(a[1]), "r"(a[2]), "r"(a[3]), "r"(b0), "r"(b1));
}

// ---------------------------------------------------------------------------
// split_hilo: fp32 [rows, 2048] -> bf16 cat [rows, 4096] (hi | lo)
// ---------------------------------------------------------------------------
__global__ void split_hilo(const float* __restrict__ in,
                           __nv_bfloat16* __restrict__ out, int rows)
{
    size_t total = (size_t)rows * (KDIM / 4);
    for (size_t i = (size_t)blockIdx.x * blockDim.x + threadIdx.x; i < total;
         i += (size_t)gridDim.x * blockDim.x) {
        size_t row = i / (KDIM / 4);
        size_t c4  = i % (KDIM / 4);
        float4 v = ((const float4*)in)[i];
        __nv_bfloat16 h0 = __float2bfloat16(v.x);
        __nv_bfloat16 h1 = __float2bfloat16(v.y);
        __nv_bfloat16 h2 = __float2bfloat16(v.z);
        __nv_bfloat16 h3 = __float2bfloat16(v.w);
        __nv_bfloat16 l0 = __float2bfloat16(v.x - __bfloat162float(h0));
        __nv_bfloat16 l1 = __float2bfloat16(v.y - __bfloat162float(h1));
        __nv_bfloat16 l2 = __float2bfloat16(v.z - __bfloat162float(h2));
        __nv_bfloat16 l3 = __float2bfloat16(v.w - __bfloat162float(h3));
        __nv_bfloat162* oh = (__nv_bfloat162*)(out + row * CATSTRIDE + c4 * 4);
        __nv_bfloat162* ol = (__nv_bfloat162*)(out + row * CATSTRIDE + KDIM + c4 * 4);
        oh[0] = __nv_bfloat162(h0, h1);
        oh[1] = __nv_bfloat162(h2, h3);
        ol[0] = __nv_bfloat162(l0, l1);
        ol[1] = __nv_bfloat162(l2, l3);
    }
}

// ---------------------------------------------------------------------------
// mma.sync split-bf16 GEMM:  C[m,n] = sum_k A[m,k]*B[n,k] + bias[n]
// A: bf16 cat [M,4096], B: bf16 cat [N,4096]. 3 accumulation terms:
//   c in [0,32):  Ahi*Bhi   c in [32,64): Ahi*Blo   c in [64,96): Alo*Bhi
// Block 128x128, BK=64 (128B rows, XOR swizzle), 8 warps (4x2), warp 32x64.
// ---------------------------------------------------------------------------
#define TBM 128
#define TBN 128
#define TBK 64
#define NCHUNK (3 * (KDIM / TBK))   // 96
#define TILE_BYTES (128 * 128)       // 16384 per operand tile
#define GEMM_SMEM (4 * TILE_BYTES)   // 65536 (A0,B0,A1,B1)

__global__ __launch_bounds__(256) void gemm_mma_split(
    const __nv_bfloat16* __restrict__ A,
    const __nv_bfloat16* __restrict__ B,
    const float* __restrict__ bias,
    float* __restrict__ C, int N)
{
    extern __shared__ char smem[];
    char* As[2] = { smem,                  smem + 2 * TILE_BYTES };
    char* Bs[2] = { smem + TILE_BYTES,     smem + 3 * TILE_BYTES };

    const int tid  = threadIdx.x;
    const int wid  = tid >> 5;
    const int lane = tid & 31;
    const int wm   = wid >> 1;         // 0..3  (M group of 32)
    const int wn   = wid & 1;          // 0..1  (N group of 64)

    const int m0 = blockIdx.x * TBM;
    const int n0 = blockIdx.y * TBN;

    const int c8  = tid & 7;           // 16B chunk in 128B row
    const int rw0 = tid >> 3;          // 0..31 (rows per pass = 32)

    float acc[2][8][4];
    #pragma unroll
    for (int i = 0; i < 2; i++)
        #pragma unroll
        for (int j = 0; j < 8; j++)
            #pragma unroll
            for (int q = 0; q < 4; q++) acc[i][j][q] = 0.0f;

    // ldmatrix per-lane swizzled offsets (byte offsets within a tile),
    // parametrized by (tile row block, k-step); row part fixed per lane.
    const int lrow = lane & 15;
    const int lhalf = (lane >> 4) * 16;  // 0 or 16 bytes (k half)

    // chunk parameters
    auto chunk_src = [&](int c, int& aOff, int& bOff, int& kt) {
        const int term = c >> 5;
        kt = c & 31;
        aOff = (term == 2) ? KDIM : 0;
        bOff = (term == 1) ? KDIM : 0;
    };

    // ---- prologue: load chunk 0 into buffer 0 ----
    {
        int aOff, bOff, kt;
        chunk_src(0, aOff, bOff, kt);
        const size_t kbase = (size_t)(kt * TBK) + c8 * 8;
        #pragma unroll
        for (int p = 0; p < 4; ++p) {
            const int row = rw0 + 32 * p;
            uint4 va = *(const uint4*)(A + (size_t)aOff + kbase + (size_t)(m0 + row) * CATSTRIDE);
            uint4 vb = *(const uint4*)(B + (size_t)bOff + kbase + (size_t)(n0 + row) * CATSTRIDE);
            uint32_t off = (uint32_t)(row * 128 + c8 * 16);
            *(uint4*)(As[0] + SMEM_SWIZZLE_128B(off)) = va;
            *(uint4*)(Bs[0] + SMEM_SWIZZLE_128B(off)) = vb;
        }
    }
    __syncthreads();

    for (int c = 0; c < NCHUNK; ++c) {
        const int s = c & 1;

        // Prefetch next chunk into registers
        uint4 av[4], bv[4];
        const bool have_next = (c + 1 < NCHUNK);
        if (have_next) {
            int aOff, bOff, kt;
            chunk_src(c + 1, aOff, bOff, kt);
            const size_t kbase = (size_t)(kt * TBK) + c8 * 8;
            #pragma unroll
            for (int p = 0; p < 4; ++p) {
                const int row = rw0 + 32 * p;
                av[p] = *(const uint4*)(A + (size_t)aOff + kbase + (size_t)(m0 + row) * CATSTRIDE);
                bv[p] = *(const uint4*)(B + (size_t)bOff + kbase + (size_t)(n0 + row) * CATSTRIDE);
            }
        }

        // Compute on buffer s
        const uint32_t aBase = smem_to_u32(As[s]);
        const uint32_t bBase = smem_to_u32(Bs[s]);
        #pragma unroll
        for (int ks = 0; ks < 4; ++ks) {
            uint32_t af[2][4];
            #pragma unroll
            for (int tm = 0; tm < 2; ++tm) {
                uint32_t off = (uint32_t)((wm * 32 + tm * 16 + lrow) * 128 + ks * 32 + lhalf);
                ldsm_x4(af[tm][0], af[tm][1], af[tm][2], af[tm][3],
                        aBase + SMEM_SWIZZLE_128B(off));
            }
            uint32_t bf[4][4];
            #pragma unroll
            for (int tn = 0; tn < 4; ++tn) {
                uint32_t off = (uint32_t)((wn * 64 + tn * 16 + lrow) * 128 + ks * 32 + lhalf);
                ldsm_x4(bf[tn][0], bf[tn][1], bf[tn][2], bf[tn][3],
                        bBase + SMEM_SWIZZLE_128B(off));
            }
            #pragma unroll
            for (int tm = 0; tm < 2; ++tm) {
                #pragma unroll
                for (int tn = 0; tn < 4; ++tn) {
                    // n8 tile 0 of this n16: regs {0,2}; tile 1: regs {1,3}
                    mma_bf16_16816(acc[tm][tn * 2 + 0], af[tm], bf[tn][0], bf[tn][2]);
                    mma_bf16_16816(acc[tm][tn * 2 + 1], af[tm], bf[tn][1], bf[tn][3]);
                }
            }
        }

        // Stage prefetched chunk into the other buffer
        if (have_next) {
            const int d = s ^ 1;
            #pragma unroll
            for (int p = 0; p < 4; ++p) {
                const int row = rw0 + 32 * p;
                uint32_t off = (uint32_t)(row * 128 + c8 * 16);
                *(uint4*)(As[d] + SMEM_SWIZZLE_128B(off)) = av[p];
                *(uint4*)(Bs[d] + SMEM_SWIZZLE_128B(off)) = bv[p];
            }
        }
        __syncthreads();
    }

    // Epilogue: c0,c1 -> (row, col..col+1); c2,c3 -> (row+8, col..col+1)
    const int rbase = m0 + wm * 32 + (lane >> 2);
    const int cbase = n0 + wn * 64 + (lane & 3) * 2;
    #pragma unroll
    for (int tm = 0; tm < 2; ++tm) {
        #pragma unroll
        for (int n8 = 0; n8 < 8; ++n8) {
            const int col = cbase + n8 * 8;
            const float b0 = bias[col], b1 = bias[col + 1];
            float* p0 = C + (size_t)(rbase + tm * 16) * N + col;
            float* p1 = p0 + (size_t)8 * N;
            float2 v0 = { acc[tm][n8][0] + b0, acc[tm][n8][1] + b1 };
            float2 v1 = { acc[tm][n8][2] + b0, acc[tm][n8][3] + b1 };
            *(float2*)p0 = v0;
            *(float2*)p1 = v1;
        }
    }
}

// ---------------------------------------------------------------------------
// Causal flash attention (fp32) — unchanged from the passing round-1 kernel
// ---------------------------------------------------------------------------
#define AT_BM 128
#define AT_BN 32
#define QS_STRIDE 132
#define SMEM_AT ((AT_BM * QS_STRIDE + 2 * AT_BN * HD) * 4)

__global__ __launch_bounds__(128, 2) void flash_attn(
    const float* __restrict__ qkv, float* __restrict__ ctx)
{
    extern __shared__ float sm[];
    float* Qs = sm;
    float* Ks = Qs + AT_BM * QS_STRIDE;
    float* Vs = Ks + AT_BN * HD;

    const int tid = threadIdx.x;
    const int q0  = blockIdx.x * AT_BM;
    const int bh  = blockIdx.y;
    const int b   = bh >> 4;
    const int h   = bh & 15;

    const size_t ROWSTRIDE = QKV_COLS;
    const float* base = qkv + (size_t)b * S_LEN * ROWSTRIDE + (size_t)h * HD;

    #pragma unroll
    for (int i = 0; i < 32; i++) {
        int idx = tid + 128 * i;
        int row = idx >> 5;
        int c4  = idx & 31;
        float4 v = *(const float4*)(base + (size_t)(q0 + row) * ROWSTRIDE + c4 * 4);
        *(float4*)(Qs + row * QS_STRIDE + c4 * 4) = v;
    }
    __syncthreads();

    const int r = q0 + tid;
    float m = -INFINITY;
    float l = 0.0f;
    float acc[HD];
    #pragma unroll
    for (int d = 0; d < HD; d++) acc[d] = 0.0f;

    const float scale = 0.08838834764831845f;

    const int nTiles = q0 / AT_BN + (AT_BM / AT_BN);
    for (int t = 0; t < nTiles; t++) {
        const int k0 = t * AT_BN;

        #pragma unroll
        for (int i = 0; i < 8; i++) {
            int idx = tid + 128 * i;
            int row = idx >> 5;
            int c4  = idx & 31;
            const float* gk = base + (size_t)(k0 + row) * ROWSTRIDE + D_MODEL + c4 * 4;
            *(float4*)(Ks + row * HD + c4 * 4) = *(const float4*)gk;
            *(float4*)(Vs + row * HD + c4 * 4) = *(const float4*)(gk + D_MODEL);
        }
        __syncthreads();

        float s[AT_BN];
        #pragma unroll
        for (int j = 0; j < AT_BN; j++) s[j] = 0.0f;

        const float4* qrow = (const float4*)(Qs + tid * QS_STRIDE);
        #pragma unroll 4
        for (int d4 = 0; d4 < HD / 4; d4++) {
            float4 q4 = qrow[d4];
            #pragma unroll
            for (int j = 0; j < AT_BN; j++) {
                float4 k4 = *(const float4*)(Ks + j * HD + d4 * 4);
                s[j] = fmaf(q4.x, k4.x,
                        fmaf(q4.y, k4.y,
                         fmaf(q4.z, k4.z,
                          fmaf(q4.w, k4.w, s[j]))));
            }
        }

        float tmax = -INFINITY;
        #pragma unroll
        for (int j = 0; j < AT_BN; j++) {
            float sv = s[j] * scale;
            if (k0 + j > r) sv = -INFINITY;
            s[j] = sv;
            tmax = fmaxf(tmax, sv);
        }

        const float newm = fmaxf(m, tmax);
        const float corr = expf(m - newm);

        float p[AT_BN];
        float psum = 0.0f;
        #pragma unroll
        for (int j = 0; j < AT_BN; j++) {
            p[j] = expf(s[j] - newm);
            psum += p[j];
        }
        l = l * corr + psum;
        m = newm;

        #pragma unroll
        for (int d = 0; d < HD; d++) acc[d] *= corr;

        #pragma unroll
        for (int j = 0; j < AT_BN; j++) {
            const float pj = p[j];
            const float4* vrow = (const float4*)(Vs + j * HD);
            #pragma unroll
            for (int d4 = 0; d4 < HD / 4; d4++) {
                float4 v4 = vrow[d4];
                acc[4 * d4 + 0] = fmaf(pj, v4.x, acc[4 * d4 + 0]);
                acc[4 * d4 + 1] = fmaf(pj, v4.y, acc[4 * d4 + 1]);
                acc[4 * d4 + 2] = fmaf(pj, v4.z, acc[4 * d4 + 2]);
                acc[4 * d4 + 3] = fmaf(pj, v4.w, acc[4 * d4 + 3]);
            }
        }
        __syncthreads();
    }

    const float inv = 1.0f / l;
    float* outp = ctx + (size_t)(b * S_LEN + r) * D_MODEL + (size_t)h * HD;
    #pragma unroll
    for (int d4 = 0; d4 < HD / 4; d4++) {
        float4 o;
        o.x = acc[4 * d4 + 0] * inv;
        o.y = acc[4 * d4 + 1] * inv;
        o.z = acc[4 * d4 + 2] * inv;
        o.w = acc[4 * d4 + 3] * inv;
        *(float4*)(outp + d4 * 4) = o;
    }
}

// ---------------------------------------------------------------------------
// kernel_launch
// ---------------------------------------------------------------------------
extern "C" void kernel_launch(void* const* d_in, const int* in_sizes, int n_in,
                              void* d_out, int out_size)
{
    (void)in_sizes; (void)n_in; (void)out_size;
    const float* x      = (const float*)d_in[0];
    const float* wqkv_w = (const float*)d_in[2];
    const float* wqkv_b = (const float*)d_in[3];
    const float* out_w  = (const float*)d_in[4];
    const float* out_b  = (const float*)d_in[5];
    float* out = (float*)d_out;

    float *qkv, *ctx;
    __nv_bfloat16 *x_cat, *wqkv_cat, *wo_cat, *ctx_cat;
    cudaGetSymbolAddress((void**)&qkv, g_qkv);
    cudaGetSymbolAddress((void**)&ctx, g_ctx);
    cudaGetSymbolAddress((void**)&x_cat, g_x_cat);
    cudaGetSymbolAddress((void**)&wqkv_cat, g_wqkv_cat);
    cudaGetSymbolAddress((void**)&wo_cat, g_wo_cat);
    cudaGetSymbolAddress((void**)&ctx_cat, g_ctx_cat);

    cudaFuncSetAttribute(gemm_mma_split,
                         cudaFuncAttributeMaxDynamicSharedMemorySize, GEMM_SMEM);
    cudaFuncSetAttribute(flash_attn,
                         cudaFuncAttributeMaxDynamicSharedMemorySize, SMEM_AT);

    // 0) hi/lo splits
    split_hilo<<<1024, 256>>>(x, x_cat, ROWS);
    split_hilo<<<1024, 256>>>(wqkv_w, wqkv_cat, QKV_COLS);
    split_hilo<<<1024, 256>>>(out_w, wo_cat, D_MODEL);

    // 1) QKV projection: [4096,2048] @ [6144,2048]^T + b -> qkv fp32
    {
        dim3 grid(ROWS / TBM, QKV_COLS / TBN);   // (32, 48)
        gemm_mma_split<<<grid, 256, GEMM_SMEM>>>(x_cat, wqkv_cat, wqkv_b, qkv,
                                                 QKV_COLS);
    }

    // 2) Causal attention
    {
        dim3 grid(S_LEN / AT_BM, B_SIZE * NHEAD);  // (16, 32)
        flash_attn<<<grid, 128, SMEM_AT>>>(qkv, ctx);
    }

    // 3) ctx split + output projection
    split_hilo<<<1024, 256>>>(ctx, ctx_cat, ROWS);
    {
        dim3 grid(ROWS / TBM, D_MODEL / TBN);    // (32, 16)
        gemm_mma_split<<<grid, 256, GEMM_SMEM>>>(ctx_cat, wo_cat, out_b, out,
                                                 D_MODEL);
    }
}

// round 9
// speedup vs baseline: 2.4192x; 1.6628x over previous
#include <cuda_runtime.h>
#include <cuda_bf16.h>
#include <math.h>
#include <stdint.h>

// Problem constants
#define B_SIZE   2
#define S_LEN    2048
#define D_MODEL  2048
#define NHEAD    16
#define HD       128
#define ROWS     (B_SIZE * S_LEN)      // 4096
#define QKV_COLS (3 * D_MODEL)         // 6144
#define KDIM     2048
#define CATSTRIDE (2 * KDIM)           // 4096 (hi block | lo block)

// ---------------------------------------------------------------------------
// Scratch (__device__ globals; no allocation allowed)
// ---------------------------------------------------------------------------
__device__ float         g_qkv[(size_t)ROWS * QKV_COLS];
__device__ float         g_ctx[(size_t)ROWS * D_MODEL];
__device__ __nv_bfloat16 g_x_cat[(size_t)ROWS * CATSTRIDE];
__device__ __nv_bfloat16 g_wqkv_cat[(size_t)QKV_COLS * CATSTRIDE];
__device__ __nv_bfloat16 g_wo_cat[(size_t)D_MODEL * CATSTRIDE];
__device__ __nv_bfloat16 g_ctx_cat[(size_t)ROWS * CATSTRIDE];
// Attention operands, [b*H+h][s][d] bf16, hi/lo
#define BHSD ((size_t)B_SIZE * NHEAD * S_LEN * HD)
__device__ __nv_bfloat16 g_Qh[BHSD];
__device__ __nv_bfloat16 g_Ql[BHSD];
__device__ __nv_bfloat16 g_Kh[BHSD];
__device__ __nv_bfloat16 g_Kl[BHSD];
__device__ __nv_bfloat16 g_Vh[BHSD];
__device__ __nv_bfloat16 g_Vl[BHSD];

#define SMEM_SWIZZLE_128B(off) ((off) ^ (((off) >> 3) & 0x70))

__device__ __forceinline__ uint32_t smem_to_u32(const void* p) {
    uint32_t a;
    asm("{ .reg .u64 t; cvta.to.shared.u64 t, %1; cvt.u32.u64 %0, t; }"
        : "=r"(a) : "l"(p));
    return a;
}
__device__ __forceinline__ void ldsm_x4(uint32_t& r0, uint32_t& r1,
                                        uint32_t& r2, uint32_t& r3,
                                        uint32_t addr) {
    asm volatile("ldmatrix.sync.aligned.m8n8.x4.shared.b16 {%0,%1,%2,%3}, [%4];"
                 : "=r"(r0), "=r"(r1), "=r"(r2), "=r"(r3) : "r"(addr));
}
__device__ __forceinline__ void ldsm_x4_t(uint32_t& r0, uint32_t& r1,
                                          uint32_t& r2, uint32_t& r3,
                                          uint32_t addr) {
    asm volatile("ldmatrix.sync.aligned.m8n8.x4.trans.shared.b16 {%0,%1,%2,%3}, [%4];"
                 : "=r"(r0), "=r"(r1), "=r"(r2), "=r"(r3) : "r"(addr));
}
__device__ __forceinline__ void mma_bf16_16816(float* c, const uint32_t* a,
                                               uint32_t b0, uint32_t b1) {
    asm volatile(
        "mma.sync.aligned.m16n8k16.row.col.f32.bf16.bf16.f32 "
        "{%0,%1,%2,%3}, {%4,%5,%6,%7}, {%8,%9}, {%0,%1,%2,%3};"
        : "+f"(c[0]), "+f"(c[1]), "+f"(c[2]), "+f"(c[3])
        : "r"(a[0]), "r"(a[1]), "r"(a[2]), "r"(a[3]), "r"(b0), "r"(b1));
}
// pack {lo, hi} fp32 -> bf16x2 register (lo in lower 16 bits)
__device__ __forceinline__ uint32_t pack_bf16x2(float lo, float hi) {
    uint32_t r;
    asm("cvt.rn.bf16x2.f32 %0, %1, %2;" : "=r"(r) : "f"(hi), "f"(lo));
    return r;
}

// ---------------------------------------------------------------------------
// split_hilo: fp32 [rows, 2048] -> bf16 cat [rows, 4096] (hi | lo)
// ---------------------------------------------------------------------------
__global__ void split_hilo(const float* __restrict__ in,
                           __nv_bfloat16* __restrict__ out, int rows)
{
    size_t total = (size_t)rows * (KDIM / 4);
    for (size_t i = (size_t)blockIdx.x * blockDim.x + threadIdx.x; i < total;
         i += (size_t)gridDim.x * blockDim.x) {
        size_t row = i / (KDIM / 4);
        size_t c4  = i % (KDIM / 4);
        float4 v = ((const float4*)in)[i];
        __nv_bfloat16 h0 = __float2bfloat16(v.x);
        __nv_bfloat16 h1 = __float2bfloat16(v.y);
        __nv_bfloat16 h2 = __float2bfloat16(v.z);
        __nv_bfloat16 h3 = __float2bfloat16(v.w);
        __nv_bfloat16 l0 = __float2bfloat16(v.x - __bfloat162float(h0));
        __nv_bfloat16 l1 = __float2bfloat16(v.y - __bfloat162float(h1));
        __nv_bfloat16 l2 = __float2bfloat16(v.z - __bfloat162float(h2));
        __nv_bfloat16 l3 = __float2bfloat16(v.w - __bfloat162float(h3));
        __nv_bfloat162* oh = (__nv_bfloat162*)(out + row * CATSTRIDE + c4 * 4);
        __nv_bfloat162* ol = (__nv_bfloat162*)(out + row * CATSTRIDE + KDIM + c4 * 4);
        oh[0] = __nv_bfloat162(h0, h1);
        oh[1] = __nv_bfloat162(h2, h3);
        ol[0] = __nv_bfloat162(l0, l1);
        ol[1] = __nv_bfloat162(l2, l3);
    }
}

// ---------------------------------------------------------------------------
// split_qkv: qkv fp32 [row,6144] -> per-(b,h) bf16 hi/lo arrays.
// Q is pre-scaled by hd^-0.5 so scores come out scaled.
// ---------------------------------------------------------------------------
__global__ void split_qkv(const float* __restrict__ qkv,
    __nv_bfloat16* __restrict__ Qh, __nv_bfloat16* __restrict__ Ql,
    __nv_bfloat16* __restrict__ Kh, __nv_bfloat16* __restrict__ Kl,
    __nv_bfloat16* __restrict__ Vh, __nv_bfloat16* __restrict__ Vl)
{
    const float scale = 0.08838834764831845f;
    const size_t total = (size_t)ROWS * (QKV_COLS / 4);
    for (size_t i = (size_t)blockIdx.x * blockDim.x + threadIdx.x; i < total;
         i += (size_t)gridDim.x * blockDim.x) {
        int row = (int)(i / (QKV_COLS / 4));
        int col = (int)(i % (QKV_COLS / 4)) * 4;
        float4 v = *(const float4*)(qkv + (size_t)row * QKV_COLS + col);
        int sect = col >> 11;           // 0=Q 1=K 2=V
        int cc   = col & 2047;
        int h    = cc >> 7, d = cc & 127;
        int b    = row >> 11, s = row & 2047;
        size_t o = (((size_t)(b * NHEAD + h)) * S_LEN + s) * HD + d;
        __nv_bfloat16 *dh, *dl;
        if (sect == 0) {
            v.x *= scale; v.y *= scale; v.z *= scale; v.w *= scale;
            dh = Qh; dl = Ql;
        } else if (sect == 1) { dh = Kh; dl = Kl; }
        else                  { dh = Vh; dl = Vl; }
        __nv_bfloat16 h0 = __float2bfloat16(v.x);
        __nv_bfloat16 h1 = __float2bfloat16(v.y);
        __nv_bfloat16 h2 = __float2bfloat16(v.z);
        __nv_bfloat16 h3 = __float2bfloat16(v.w);
        __nv_bfloat162* ph = (__nv_bfloat162*)(dh + o);
        __nv_bfloat162* pl = (__nv_bfloat162*)(dl + o);
        ph[0] = __nv_bfloat162(h0, h1);
        ph[1] = __nv_bfloat162(h2, h3);
        pl[0] = __nv_bfloat162(__float2bfloat16(v.x - __bfloat162float(h0)),
                               __float2bfloat16(v.y - __bfloat162float(h1)));
        pl[1] = __nv_bfloat162(__float2bfloat16(v.z - __bfloat162float(h2)),
                               __float2bfloat16(v.w - __bfloat162float(h3)));
    }
}

// ---------------------------------------------------------------------------
// mma.sync split-bf16 GEMM (unchanged from round 6, passing)
// ---------------------------------------------------------------------------
#define TBM 128
#define TBN 128
#define TBK 64
#define NCHUNK (3 * (KDIM / TBK))
#define TILE_BYTES (128 * 128)
#define GEMM_SMEM (4 * TILE_BYTES)

__global__ __launch_bounds__(256) void gemm_mma_split(
    const __nv_bfloat16* __restrict__ A,
    const __nv_bfloat16* __restrict__ B,
    const float* __restrict__ bias,
    float* __restrict__ C, int N)
{
    extern __shared__ char smem[];
    char* As[2] = { smem,              smem + 2 * TILE_BYTES };
    char* Bs[2] = { smem + TILE_BYTES, smem + 3 * TILE_BYTES };

    const int tid  = threadIdx.x;
    const int wid  = tid >> 5;
    const int lane = tid & 31;
    const int wm   = wid >> 1;
    const int wn   = wid & 1;

    const int m0 = blockIdx.x * TBM;
    const int n0 = blockIdx.y * TBN;

    const int c8  = tid & 7;
    const int rw0 = tid >> 3;

    float acc[2][8][4];
    #pragma unroll
    for (int i = 0; i < 2; i++)
        #pragma unroll
        for (int j = 0; j < 8; j++)
            #pragma unroll
            for (int q = 0; q < 4; q++) acc[i][j][q] = 0.0f;

    const int lrow = lane & 15;
    const int lhalf = (lane >> 4) * 16;

    auto chunk_src = [&](int c, int& aOff, int& bOff, int& kt) {
        const int term = c >> 5;
        kt = c & 31;
        aOff = (term == 2) ? KDIM : 0;
        bOff = (term == 1) ? KDIM : 0;
    };

    {
        int aOff, bOff, kt;
        chunk_src(0, aOff, bOff, kt);
        const size_t kbase = (size_t)(kt * TBK) + c8 * 8;
        #pragma unroll
        for (int p = 0; p < 4; ++p) {
            const int row = rw0 + 32 * p;
            uint4 va = *(const uint4*)(A + (size_t)aOff + kbase + (size_t)(m0 + row) * CATSTRIDE);
            uint4 vb = *(const uint4*)(B + (size_t)bOff + kbase + (size_t)(n0 + row) * CATSTRIDE);
            uint32_t off = (uint32_t)(row * 128 + c8 * 16);
            *(uint4*)(As[0] + SMEM_SWIZZLE_128B(off)) = va;
            *(uint4*)(Bs[0] + SMEM_SWIZZLE_128B(off)) = vb;
        }
    }
    __syncthreads();

    for (int c = 0; c < NCHUNK; ++c) {
        const int s = c & 1;

        uint4 av[4], bv[4];
        const bool have_next = (c + 1 < NCHUNK);
        if (have_next) {
            int aOff, bOff, kt;
            chunk_src(c + 1, aOff, bOff, kt);
            const size_t kbase = (size_t)(kt * TBK) + c8 * 8;
            #pragma unroll
            for (int p = 0; p < 4; ++p) {
                const int row = rw0 + 32 * p;
                av[p] = *(const uint4*)(A + (size_t)aOff + kbase + (size_t)(m0 + row) * CATSTRIDE);
                bv[p] = *(const uint4*)(B + (size_t)bOff + kbase + (size_t)(n0 + row) * CATSTRIDE);
            }
        }

        const uint32_t aBase = smem_to_u32(As[s]);
        const uint32_t bBase = smem_to_u32(Bs[s]);
        #pragma unroll
        for (int ks = 0; ks < 4; ++ks) {
            uint32_t af[2][4];
            #pragma unroll
            for (int tm = 0; tm < 2; ++tm) {
                uint32_t off = (uint32_t)((wm * 32 + tm * 16 + lrow) * 128 + ks * 32 + lhalf);
                ldsm_x4(af[tm][0], af[tm][1], af[tm][2], af[tm][3],
                        aBase + SMEM_SWIZZLE_128B(off));
            }
            uint32_t bf[4][4];
            #pragma unroll
            for (int tn = 0; tn < 4; ++tn) {
                uint32_t off = (uint32_t)((wn * 64 + tn * 16 + lrow) * 128 + ks * 32 + lhalf);
                ldsm_x4(bf[tn][0], bf[tn][1], bf[tn][2], bf[tn][3],
                        bBase + SMEM_SWIZZLE_128B(off));
            }
            #pragma unroll
            for (int tm = 0; tm < 2; ++tm) {
                #pragma unroll
                for (int tn = 0; tn < 4; ++tn) {
                    mma_bf16_16816(acc[tm][tn * 2 + 0], af[tm], bf[tn][0], bf[tn][2]);
                    mma_bf16_16816(acc[tm][tn * 2 + 1], af[tm], bf[tn][1], bf[tn][3]);
                }
            }
        }

        if (have_next) {
            const int d = s ^ 1;
            #pragma unroll
            for (int p = 0; p < 4; ++p) {
                const int row = rw0 + 32 * p;
                uint32_t off = (uint32_t)(row * 128 + c8 * 16);
                *(uint4*)(As[d] + SMEM_SWIZZLE_128B(off)) = av[p];
                *(uint4*)(Bs[d] + SMEM_SWIZZLE_128B(off)) = bv[p];
            }
        }
        __syncthreads();
    }

    const int rbase = m0 + wm * 32 + (lane >> 2);
    const int cbase = n0 + wn * 64 + (lane & 3) * 2;
    #pragma unroll
    for (int tm = 0; tm < 2; ++tm) {
        #pragma unroll
        for (int n8 = 0; n8 < 8; ++n8) {
            const int col = cbase + n8 * 8;
            const float b0 = bias[col], b1 = bias[col + 1];
            float* p0 = C + (size_t)(rbase + tm * 16) * N + col;
            float* p1 = p0 + (size_t)8 * N;
            float2 v0 = { acc[tm][n8][0] + b0, acc[tm][n8][1] + b1 };
            float2 v1 = { acc[tm][n8][2] + b0, acc[tm][n8][3] + b1 };
            *(float2*)p0 = v0;
            *(float2*)p1 = v1;
        }
    }
}

// ---------------------------------------------------------------------------
// Tensor-core causal flash attention (split-bf16, 3-term QK and PV).
// CTA: 128 q-rows, 8 warps x 16 rows. Key tile = 64. hd = 128.
// Smem: Khi|Klo|Vhi|Vlo, 64 rows x 256B, swizzled 16B chunks.
// ---------------------------------------------------------------------------
#define FA_BN 64
#define KV_TILE (FA_BN * 256)          // 16384 bytes
#define FA_SMEM (4 * KV_TILE)          // 65536

__device__ __forceinline__ uint32_t swz256(int r, int c) {
    return (uint32_t)(r * 256 + (((c ^ r) & 7) | (c & 8)) * 16);
}

__global__ __launch_bounds__(256) void flash_attn_tc(
    const __nv_bfloat16* __restrict__ Qh, const __nv_bfloat16* __restrict__ Ql,
    const __nv_bfloat16* __restrict__ Kh, const __nv_bfloat16* __restrict__ Kl,
    const __nv_bfloat16* __restrict__ Vh, const __nv_bfloat16* __restrict__ Vl,
    float* __restrict__ ctx)
{
    extern __shared__ char sm[];
    char* Khs = sm;
    char* Kls = sm + KV_TILE;
    char* Vhs = sm + 2 * KV_TILE;
    char* Vls = sm + 3 * KV_TILE;

    const int tid  = threadIdx.x;
    const int wid  = tid >> 5;
    const int lane = tid & 31;
    const int q0   = (int)(gridDim.x - 1 - blockIdx.x) * 128;  // long CTAs first
    const int bh   = blockIdx.y;
    const size_t bhoff = (size_t)bh * S_LEN * HD;

    // --- Q fragments (persistent in registers) ---
    const int r0 = wid * 16 + (lane >> 2);
    uint32_t qh[8][4], ql[8][4];
    {
        const int kcol = (lane & 3) * 2;
        #pragma unroll
        for (int kc = 0; kc < 8; ++kc) {
            const size_t base = bhoff + (size_t)(q0 + r0) * HD + kc * 16 + kcol;
            qh[kc][0] = *(const uint32_t*)(Qh + base);
            qh[kc][1] = *(const uint32_t*)(Qh + base + 8 * HD);
            qh[kc][2] = *(const uint32_t*)(Qh + base + 8);
            qh[kc][3] = *(const uint32_t*)(Qh + base + 8 * HD + 8);
            ql[kc][0] = *(const uint32_t*)(Ql + base);
            ql[kc][1] = *(const uint32_t*)(Ql + base + 8 * HD);
            ql[kc][2] = *(const uint32_t*)(Ql + base + 8);
            ql[kc][3] = *(const uint32_t*)(Ql + base + 8 * HD + 8);
        }
    }

    float o[16][4];
    #pragma unroll
    for (int n = 0; n < 16; ++n)
        #pragma unroll
        for (int j = 0; j < 4; ++j) o[n][j] = 0.0f;
    float m0 = -INFINITY, m1 = -INFINITY, l0 = 0.0f, l1 = 0.0f;

    const int rowg0 = q0 + r0;
    const int rowg1 = rowg0 + 8;
    const int nTiles = q0 / FA_BN + 2;

    const uint32_t khB = smem_to_u32(Khs);
    const uint32_t klB = smem_to_u32(Kls);
    const uint32_t vhB = smem_to_u32(Vhs);
    const uint32_t vlB = smem_to_u32(Vls);

    for (int t = 0; t < nTiles; ++t) {
        const int k0 = t * FA_BN;

        // --- cooperative K/V tile load (64 rows x 16 chunks per array) ---
        #pragma unroll
        for (int p = 0; p < 4; ++p) {
            const int idx = tid + 256 * p;
            const int row = idx >> 4;
            const int c   = idx & 15;
            const size_t g = bhoff + (size_t)(k0 + row) * HD + c * 8;
            const uint32_t so = swz256(row, c);
            *(uint4*)(Khs + so) = *(const uint4*)(Kh + g);
            *(uint4*)(Kls + so) = *(const uint4*)(Kl + g);
            *(uint4*)(Vhs + so) = *(const uint4*)(Vh + g);
            *(uint4*)(Vls + so) = *(const uint4*)(Vl + g);
        }
        __syncthreads();

        // --- S = Q K^T (3 terms) ---
        float s[8][4];
        #pragma unroll
        for (int n = 0; n < 8; ++n)
            #pragma unroll
            for (int j = 0; j < 4; ++j) s[n][j] = 0.0f;

        #pragma unroll
        for (int kc = 0; kc < 8; ++kc) {
            #pragma unroll
            for (int g = 0; g < 4; ++g) {
                uint32_t h0, h1, h2, h3, e0, e1, e2, e3;
                const uint32_t off = swz256(g * 16 + (lane & 15), kc * 2 + (lane >> 4));
                ldsm_x4(h0, h1, h2, h3, khB + off);
                ldsm_x4(e0, e1, e2, e3, klB + off);
                mma_bf16_16816(s[2 * g + 0], qh[kc], h0, h2);
                mma_bf16_16816(s[2 * g + 1], qh[kc], h1, h3);
                mma_bf16_16816(s[2 * g + 0], qh[kc], e0, e2);
                mma_bf16_16816(s[2 * g + 1], qh[kc], e1, e3);
                mma_bf16_16816(s[2 * g + 0], ql[kc], h0, h2);
                mma_bf16_16816(s[2 * g + 1], ql[kc], h1, h3);
            }
        }

        // --- causal mask (only tiles overlapping the diagonal for this warp) ---
        if (k0 + FA_BN - 1 > q0 + wid * 16) {
            #pragma unroll
            for (int n = 0; n < 8; ++n) {
                const int cb = k0 + n * 8 + (lane & 3) * 2;
                if (cb     > rowg0) s[n][0] = -INFINITY;
                if (cb + 1 > rowg0) s[n][1] = -INFINITY;
                if (cb     > rowg1) s[n][2] = -INFINITY;
                if (cb + 1 > rowg1) s[n][3] = -INFINITY;
            }
        }

        // --- online softmax ---
        float t0 = -INFINITY, t1 = -INFINITY;
        #pragma unroll
        for (int n = 0; n < 8; ++n) {
            t0 = fmaxf(t0, fmaxf(s[n][0], s[n][1]));
            t1 = fmaxf(t1, fmaxf(s[n][2], s[n][3]));
        }
        t0 = fmaxf(t0, __shfl_xor_sync(0xFFFFFFFF, t0, 1));
        t0 = fmaxf(t0, __shfl_xor_sync(0xFFFFFFFF, t0, 2));
        t1 = fmaxf(t1, __shfl_xor_sync(0xFFFFFFFF, t1, 1));
        t1 = fmaxf(t1, __shfl_xor_sync(0xFFFFFFFF, t1, 2));
        const float nm0 = fmaxf(m0, t0), nm1 = fmaxf(m1, t1);
        const float co0 = __expf(m0 - nm0), co1 = __expf(m1 - nm1);
        m0 = nm0; m1 = nm1;

        #pragma unroll
        for (int n = 0; n < 16; ++n) {
            o[n][0] *= co0; o[n][1] *= co0;
            o[n][2] *= co1; o[n][3] *= co1;
        }
        float ps0 = 0.0f, ps1 = 0.0f;
        #pragma unroll
        for (int n = 0; n < 8; ++n) {
            s[n][0] = __expf(s[n][0] - nm0);
            s[n][1] = __expf(s[n][1] - nm0);
            s[n][2] = __expf(s[n][2] - nm1);
            s[n][3] = __expf(s[n][3] - nm1);
            ps0 += s[n][0] + s[n][1];
            ps1 += s[n][2] + s[n][3];
        }
        l0 = l0 * co0 + ps0;
        l1 = l1 * co1 + ps1;

        // --- O += P V (3 terms) ---
        #pragma unroll
        for (int kk = 0; kk < 4; ++kk) {
            uint32_t ah[4], al[4];
            {
                const float* pa = s[2 * kk];
                const float* pb = s[2 * kk + 1];
                float hv, lv0, lv1;
                hv = __bfloat162float(__float2bfloat16(pa[0])); lv0 = pa[0] - hv;
                float hv1 = __bfloat162float(__float2bfloat16(pa[1])); lv1 = pa[1] - hv1;
                ah[0] = pack_bf16x2(hv, hv1); al[0] = pack_bf16x2(lv0, lv1);
                hv = __bfloat162float(__float2bfloat16(pa[2])); lv0 = pa[2] - hv;
                hv1 = __bfloat162float(__float2bfloat16(pa[3])); lv1 = pa[3] - hv1;
                ah[1] = pack_bf16x2(hv, hv1); al[1] = pack_bf16x2(lv0, lv1);
                hv = __bfloat162float(__float2bfloat16(pb[0])); lv0 = pb[0] - hv;
                hv1 = __bfloat162float(__float2bfloat16(pb[1])); lv1 = pb[1] - hv1;
                ah[2] = pack_bf16x2(hv, hv1); al[2] = pack_bf16x2(lv0, lv1);
                hv = __bfloat162float(__float2bfloat16(pb[2])); lv0 = pb[2] - hv;
                hv1 = __bfloat162float(__float2bfloat16(pb[3])); lv1 = pb[3] - hv1;
                ah[3] = pack_bf16x2(hv, hv1); al[3] = pack_bf16x2(lv0, lv1);
            }
            const int vrow = kk * 16 + ((lane >> 3) & 1) * 8 + (lane & 7);
            #pragma unroll
            for (int dt = 0; dt < 8; ++dt) {
                uint32_t w0, w1, w2, w3, x0, x1, x2, x3;
                const uint32_t off = swz256(vrow, dt * 2 + (lane >> 4));
                ldsm_x4_t(w0, w1, w2, w3, vhB + off);
                ldsm_x4_t(x0, x1, x2, x3, vlB + off);
                mma_bf16_16816(o[2 * dt + 0], ah, w0, w1);
                mma_bf16_16816(o[2 * dt + 1], ah, w2, w3);
                mma_bf16_16816(o[2 * dt + 0], ah, x0, x1);
                mma_bf16_16816(o[2 * dt + 1], ah, x2, x3);
                mma_bf16_16816(o[2 * dt + 0], al, w0, w1);
                mma_bf16_16816(o[2 * dt + 1], al, w2, w3);
            }
        }
        __syncthreads();
    }

    // --- finalize: row-sum across the quad, normalize, store ---
    l0 += __shfl_xor_sync(0xFFFFFFFF, l0, 1);
    l0 += __shfl_xor_sync(0xFFFFFFFF, l0, 2);
    l1 += __shfl_xor_sync(0xFFFFFFFF, l1, 1);
    l1 += __shfl_xor_sync(0xFFFFFFFF, l1, 2);
    const float inv0 = 1.0f / l0, inv1 = 1.0f / l1;

    const int b = bh >> 4, h = bh & 15;
    const int colb = h * HD + (lane & 3) * 2;
    float* base0 = g_ctx + (size_t)(b * S_LEN + rowg0) * D_MODEL + colb;
    float* base1 = g_ctx + (size_t)(b * S_LEN + rowg1) * D_MODEL + colb;
    (void)ctx;
    #pragma unroll
    for (int n = 0; n < 16; ++n) {
        float2 v0 = { o[n][0] * inv0, o[n][1] * inv0 };
        float2 v1 = { o[n][2] * inv1, o[n][3] * inv1 };
        *(float2*)(base0 + n * 8) = v0;
        *(float2*)(base1 + n * 8) = v1;
    }
}

// ---------------------------------------------------------------------------
// kernel_launch
// ---------------------------------------------------------------------------
extern "C" void kernel_launch(void* const* d_in, const int* in_sizes, int n_in,
                              void* d_out, int out_size)
{
    (void)in_sizes; (void)n_in; (void)out_size;
    const float* x      = (const float*)d_in[0];
    const float* wqkv_w = (const float*)d_in[2];
    const float* wqkv_b = (const float*)d_in[3];
    const float* out_w  = (const float*)d_in[4];
    const float* out_b  = (const float*)d_in[5];
    float* out = (float*)d_out;

    float *qkv, *ctx;
    __nv_bfloat16 *x_cat, *wqkv_cat, *wo_cat, *ctx_cat;
    __nv_bfloat16 *Qh, *Ql, *Kh, *Kl, *Vh, *Vl;
    cudaGetSymbolAddress((void**)&qkv, g_qkv);
    cudaGetSymbolAddress((void**)&ctx, g_ctx);
    cudaGetSymbolAddress((void**)&x_cat, g_x_cat);
    cudaGetSymbolAddress((void**)&wqkv_cat, g_wqkv_cat);
    cudaGetSymbolAddress((void**)&wo_cat, g_wo_cat);
    cudaGetSymbolAddress((void**)&ctx_cat, g_ctx_cat);
    cudaGetSymbolAddress((void**)&Qh, g_Qh);
    cudaGetSymbolAddress((void**)&Ql, g_Ql);
    cudaGetSymbolAddress((void**)&Kh, g_Kh);
    cudaGetSymbolAddress((void**)&Kl, g_Kl);
    cudaGetSymbolAddress((void**)&Vh, g_Vh);
    cudaGetSymbolAddress((void**)&Vl, g_Vl);

    cudaFuncSetAttribute(gemm_mma_split,
                         cudaFuncAttributeMaxDynamicSharedMemorySize, GEMM_SMEM);
    cudaFuncSetAttribute(flash_attn_tc,
                         cudaFuncAttributeMaxDynamicSharedMemorySize, FA_SMEM);

    // 0) hi/lo splits of GEMM operands
    split_hilo<<<1024, 256>>>(x, x_cat, ROWS);
    split_hilo<<<1024, 256>>>(wqkv_w, wqkv_cat, QKV_COLS);
    split_hilo<<<1024, 256>>>(out_w, wo_cat, D_MODEL);

    // 1) QKV projection -> qkv fp32
    {
        dim3 grid(ROWS / TBM, QKV_COLS / TBN);
        gemm_mma_split<<<grid, 256, GEMM_SMEM>>>(x_cat, wqkv_cat, wqkv_b, qkv,
                                                 QKV_COLS);
    }

    // 2) split qkv into per-head bf16 hi/lo operands
    split_qkv<<<2048, 256>>>(qkv, Qh, Ql, Kh, Kl, Vh, Vl);

    // 3) tensor-core causal attention -> ctx fp32
    {
        dim3 grid(S_LEN / 128, B_SIZE * NHEAD);
        flash_attn_tc<<<grid, 256, FA_SMEM>>>(Qh, Ql, Kh, Kl, Vh, Vl, ctx);
    }

    // 4) ctx split + output projection
    split_hilo<<<1024, 256>>>(ctx, ctx_cat, ROWS);
    {
        dim3 grid(ROWS / TBM, D_MODEL / TBN);
        gemm_mma_split<<<grid, 256, GEMM_SMEM>>>(ctx_cat, wo_cat, out_b, out,
                                                 D_MODEL);
    }
}